// round 5
// baseline (speedup 1.0000x reference)
#include <cuda_runtime.h>

// l,r: [N, C, H, W] = [2, 32, 128, 256] fp32
// out: [N, C, D, H, W], D = 48
// out[n,c,d,h,w] = (w >= d) ? l[n,c,h,w] - r[n,c,h,w-d] : 1.0f
#define NB   2
#define CC   32
#define HH   128
#define WW   256
#define DD   48
#define NC   (NB * CC)        // 64 fused n*C+c planes
#define NROWS (NC * HH)       // 8192 (nc,h) rows; row = nc*HH + h
#define PAD  64               // front pad (max negative window index is -48)
#define RPB  2                // rows per block (128 threads / 64 lanes)

// One block = 2 rows x 64 lanes (128 threads). Each thread owns one w-quad
// (w0 = 4*lane) and emits ALL 48 disparities for it. Per iteration i the
// aligned quad pair
//   B = rs[w0-4i .. +3],  A = rs[w0-4i-4 .. +3]
// supplies windows for d = 4i+0..3 via pure register selection.
// 13 LDS.128 + 48 STG.128 per thread; no redundant shared reads.
// Plain stores (no .cs): write-once stream with fully covered 128B sectors;
// evict-normal lets L2 batch writebacks into larger DRAM bursts.
__global__ __launch_bounds__(128) void cost_volume_kernel(
    const float* __restrict__ l,
    const float* __restrict__ r,
    float* __restrict__ out)
{
    __shared__ float rs_s[RPB][PAD + WW];

    const int tid  = threadIdx.x;
    const int lr   = tid >> 6;               // local row 0..1
    const int lane = tid & 63;               // w-quad index
    const int row  = blockIdx.x * RPB + lr;  // 0 .. NROWS-1
    const int nc   = row >> 7;
    const int h    = row & (HH - 1);

    float* rs = &rs_s[lr][PAD];
    const size_t in_base = (size_t)row * WW;
    const int w0 = lane << 2;

    // Stage this row's r into shared (one LDG.128 + STS.128 per thread).
    *reinterpret_cast<float4*>(rs + w0) =
        *reinterpret_cast<const float4*>(r + in_base + w0);
    if (lane < PAD / 4)                       // zero the 64-float front pad
        reinterpret_cast<float4*>(&rs_s[lr][0])[lane] = make_float4(0.f, 0.f, 0.f, 0.f);

    // l-quad straight from gmem (private to this thread).
    const float4 lv = *reinterpret_cast<const float4*>(l + in_base + w0);
    __syncthreads();

    float4 B = *reinterpret_cast<const float4*>(rs + w0);

    float* obase = out + ((size_t)nc * DD * HH + h) * WW + w0;
    const size_t dstride = (size_t)HH * WW;

    #pragma unroll
    for (int i = 0; i < DD / 4; ++i) {
        const float4 A = *reinterpret_cast<const float4*>(rs + w0 - 4 * i - 4);
        const float win[8] = { A.x, A.y, A.z, A.w, B.x, B.y, B.z, B.w };
        // win[4 - dg + j] == rs[w0 - (4i+dg) + j]
        #pragma unroll
        for (int dg = 0; dg < 4; ++dg) {
            const int d = 4 * i + dg;
            float4 o;
            o.x = (w0 + 0 >= d) ? lv.x - win[4 - dg + 0] : 1.0f;
            o.y = (w0 + 1 >= d) ? lv.y - win[4 - dg + 1] : 1.0f;
            o.z = (w0 + 2 >= d) ? lv.z - win[4 - dg + 2] : 1.0f;
            o.w = (w0 + 3 >= d) ? lv.w - win[4 - dg + 3] : 1.0f;
            *reinterpret_cast<float4*>(obase + (size_t)d * dstride) = o;
        }
        B = A;
    }
}

extern "C" void kernel_launch(void* const* d_in, const int* in_sizes, int n_in,
                              void* d_out, int out_size)
{
    (void)in_sizes; (void)n_in; (void)out_size;
    const float* l = (const float*)d_in[0];
    const float* r = (const float*)d_in[1];
    float* out = (float*)d_out;

    cost_volume_kernel<<<NROWS / RPB, 128>>>(l, r, out);
}